// round 3
// baseline (speedup 1.0000x reference)
#include <cuda_runtime.h>
#include <cuda_bf16.h>
#include <math.h>

// ---------------- problem constants ----------------
#define BATCH 4
#define SEQ   2048
#define DIM   512
#define NHEAD 8
#define HDIM  64
#define FFN   2048
#define MTOT  (BATCH * SEQ)          // 8192 rows

// ---------------- scratch (no allocation allowed) ----------------
__device__ float g_q  [MTOT * DIM];
__device__ float g_k  [MTOT * DIM];
__device__ float g_v  [MTOT * DIM];
__device__ float g_att[MTOT * DIM];
__device__ float g_y1 [MTOT * DIM];
__device__ float g_x1 [MTOT * DIM];
__device__ float g_h  [MTOT * FFN];
__device__ float g_y2 [MTOT * DIM];

// ---------------- generic tiled SGEMM ----------------
// C[M,N] = A[M,K] @ B[K,N] + bias[N]  (+ residual / gelu epilogues)
// BM=BN=64, BK=16, 256 threads, 4x4 per-thread microtile.
// EPI: 0 = bias, 1 = bias + residual, 2 = bias + exact GELU
#define BM 64
#define BN 64
#define BK 16

__device__ __forceinline__ float gelu_exact(float v) {
    return 0.5f * v * (1.0f + erff(v * 0.70710678118654752f));
}

template<int EPI>
__global__ __launch_bounds__(256) void gemm_kernel(
    const float* __restrict__ A, const float* __restrict__ B,
    const float* __restrict__ bias, const float* __restrict__ res,
    float* __restrict__ C, int M, int N, int K)
{
    __shared__ float As[BK][BM + 1];   // A staged transposed (k-major)
    __shared__ float Bs[BK][BN];       // B staged row-major (float4-readable)

    const int tid = threadIdx.x;
    const int tx  = tid & 15;          // 0..15 -> col group
    const int ty  = tid >> 4;          // 0..15 -> row group
    const int rowBase = blockIdx.y * BM;
    const int colBase = blockIdx.x * BN;

    // load mapping: A tile 64x16, each thread one float4
    const int aRow = tid >> 2;         // 0..63
    const int aCol = (tid & 3) * 4;    // 0,4,8,12
    // B tile 16x64
    const int bRow = tid >> 4;         // 0..15
    const int bCol = (tid & 15) * 4;   // 0..60

    float acc[4][4] = {};

    for (int k0 = 0; k0 < K; k0 += BK) {
        float4 av = *(const float4*)(A + (size_t)(rowBase + aRow) * K + k0 + aCol);
        As[aCol + 0][aRow] = av.x;
        As[aCol + 1][aRow] = av.y;
        As[aCol + 2][aRow] = av.z;
        As[aCol + 3][aRow] = av.w;
        *(float4*)&Bs[bRow][bCol] =
            *(const float4*)(B + (size_t)(k0 + bRow) * N + colBase + bCol);
        __syncthreads();

        #pragma unroll
        for (int kk = 0; kk < BK; kk++) {
            float a0 = As[kk][ty * 4 + 0];
            float a1 = As[kk][ty * 4 + 1];
            float a2 = As[kk][ty * 4 + 2];
            float a3 = As[kk][ty * 4 + 3];
            float4 bv = *(const float4*)&Bs[kk][tx * 4];
            acc[0][0] = fmaf(a0, bv.x, acc[0][0]); acc[0][1] = fmaf(a0, bv.y, acc[0][1]);
            acc[0][2] = fmaf(a0, bv.z, acc[0][2]); acc[0][3] = fmaf(a0, bv.w, acc[0][3]);
            acc[1][0] = fmaf(a1, bv.x, acc[1][0]); acc[1][1] = fmaf(a1, bv.y, acc[1][1]);
            acc[1][2] = fmaf(a1, bv.z, acc[1][2]); acc[1][3] = fmaf(a1, bv.w, acc[1][3]);
            acc[2][0] = fmaf(a2, bv.x, acc[2][0]); acc[2][1] = fmaf(a2, bv.y, acc[2][1]);
            acc[2][2] = fmaf(a2, bv.z, acc[2][2]); acc[2][3] = fmaf(a2, bv.w, acc[2][3]);
            acc[3][0] = fmaf(a3, bv.x, acc[3][0]); acc[3][1] = fmaf(a3, bv.y, acc[3][1]);
            acc[3][2] = fmaf(a3, bv.z, acc[3][2]); acc[3][3] = fmaf(a3, bv.w, acc[3][3]);
        }
        __syncthreads();
    }

    #pragma unroll
    for (int i = 0; i < 4; i++) {
        int r = rowBase + ty * 4 + i;
        #pragma unroll
        for (int j = 0; j < 4; j++) {
            int c = colBase + tx * 4 + j;
            float v = acc[i][j] + bias[c];
            if (EPI == 1) v += res[(size_t)r * N + c];
            if (EPI == 2) v = gelu_exact(v);
            C[(size_t)r * N + c] = v;
        }
    }
}

// ---------------- flash attention (fp32) ----------------
// grid: (SEQ/AQ, BATCH*NHEAD), 256 threads.
// Q/K/V layout: [BATCH*SEQ, DIM] row-major; head h occupies cols [h*64, h*64+64)
#define AQ 64
#define AK 32

__global__ __launch_bounds__(256) void attn_kernel(
    const float* __restrict__ Q, const float* __restrict__ K,
    const float* __restrict__ V, float* __restrict__ O)
{
    __shared__ float Qs[HDIM][AQ + 1];   // [d][q]
    __shared__ float Ks[HDIM][AK + 1];   // [d][k]
    __shared__ float Vs[AK][HDIM];       // [k][d]
    __shared__ float Ss[AK][AQ + 1];     // [k][q] : scores then probs
    __shared__ float mrow[AQ], lrow[AQ], arow[AQ];

    const int tid = threadIdx.x;
    const int tx = tid & 15;   // col group
    const int ty = tid >> 4;   // row group
    const int bh = blockIdx.y;
    const int b  = bh >> 3;
    const int h  = bh & 7;
    const int q0 = blockIdx.x * AQ;
    const float scale = 0.125f;  // 1/sqrt(64)

    const float* Qb = Q + (size_t)b * SEQ * DIM + (size_t)h * HDIM;
    const float* Kb = K + (size_t)b * SEQ * DIM + (size_t)h * HDIM;
    const float* Vb = V + (size_t)b * SEQ * DIM + (size_t)h * HDIM;

    // load Q tile (transposed)
    for (int i = tid; i < AQ * HDIM; i += 256) {
        int q = i >> 6, d = i & 63;
        Qs[d][q] = Qb[(size_t)(q0 + q) * DIM + d];
    }
    if (tid < AQ) { mrow[tid] = -1e30f; lrow[tid] = 0.0f; }

    float o[4][4] = {};

    for (int t = 0; t < SEQ / AK; t++) {
        __syncthreads();  // protect Ks/Vs/Ss reuse (and Q/stats init on t==0)
        for (int i = tid; i < AK * HDIM; i += 256) {
            int kr = i >> 6, d = i & 63;
            float kv = Kb[(size_t)(t * AK + kr) * DIM + d];
            float vv = Vb[(size_t)(t * AK + kr) * DIM + d];
            Ks[d][kr] = kv;
            Vs[kr][d] = vv;
        }
        __syncthreads();

        // S = Q @ K^T : thread computes rows ty*4..+3, keys tx*2..+1
        float s[4][2] = {};
        #pragma unroll 8
        for (int d = 0; d < HDIM; d++) {
            float a0 = Qs[d][ty * 4 + 0];
            float a1 = Qs[d][ty * 4 + 1];
            float a2 = Qs[d][ty * 4 + 2];
            float a3 = Qs[d][ty * 4 + 3];
            float b0 = Ks[d][tx * 2 + 0];
            float b1 = Ks[d][tx * 2 + 1];
            s[0][0] = fmaf(a0, b0, s[0][0]); s[0][1] = fmaf(a0, b1, s[0][1]);
            s[1][0] = fmaf(a1, b0, s[1][0]); s[1][1] = fmaf(a1, b1, s[1][1]);
            s[2][0] = fmaf(a2, b0, s[2][0]); s[2][1] = fmaf(a2, b1, s[2][1]);
            s[3][0] = fmaf(a3, b0, s[3][0]); s[3][1] = fmaf(a3, b1, s[3][1]);
        }
        #pragma unroll
        for (int i = 0; i < 4; i++)
            #pragma unroll
            for (int j = 0; j < 2; j++)
                Ss[tx * 2 + j][ty * 4 + i] = s[i][j] * scale;
        __syncthreads();

        // online softmax, one thread per query row
        if (tid < AQ) {
            int r = tid;
            float mold = mrow[r], mx = mold;
            #pragma unroll
            for (int j = 0; j < AK; j++) mx = fmaxf(mx, Ss[j][r]);
            float sum = 0.0f;
            #pragma unroll
            for (int j = 0; j < AK; j++) {
                float p = __expf(Ss[j][r] - mx);
                Ss[j][r] = p;
                sum += p;
            }
            float al = __expf(mold - mx);
            arow[r] = al;
            lrow[r] = lrow[r] * al + sum;
            mrow[r] = mx;
        }
        __syncthreads();

        // O = O*alpha + P @ V
        float al0 = arow[ty * 4 + 0], al1 = arow[ty * 4 + 1];
        float al2 = arow[ty * 4 + 2], al3 = arow[ty * 4 + 3];
        #pragma unroll
        for (int j = 0; j < 4; j++) {
            o[0][j] *= al0; o[1][j] *= al1; o[2][j] *= al2; o[3][j] *= al3;
        }
        #pragma unroll 4
        for (int kk = 0; kk < AK; kk++) {
            float a0 = Ss[kk][ty * 4 + 0];
            float a1 = Ss[kk][ty * 4 + 1];
            float a2 = Ss[kk][ty * 4 + 2];
            float a3 = Ss[kk][ty * 4 + 3];
            float4 bv = *(const float4*)&Vs[kk][tx * 4];
            o[0][0] = fmaf(a0, bv.x, o[0][0]); o[0][1] = fmaf(a0, bv.y, o[0][1]);
            o[0][2] = fmaf(a0, bv.z, o[0][2]); o[0][3] = fmaf(a0, bv.w, o[0][3]);
            o[1][0] = fmaf(a1, bv.x, o[1][0]); o[1][1] = fmaf(a1, bv.y, o[1][1]);
            o[1][2] = fmaf(a1, bv.z, o[1][2]); o[1][3] = fmaf(a1, bv.w, o[1][3]);
            o[2][0] = fmaf(a2, bv.x, o[2][0]); o[2][1] = fmaf(a2, bv.y, o[2][1]);
            o[2][2] = fmaf(a2, bv.z, o[2][2]); o[2][3] = fmaf(a2, bv.w, o[2][3]);
            o[3][0] = fmaf(a3, bv.x, o[3][0]); o[3][1] = fmaf(a3, bv.y, o[3][1]);
            o[3][2] = fmaf(a3, bv.z, o[3][2]); o[3][3] = fmaf(a3, bv.w, o[3][3]);
        }
    }

    // normalize and write: out[(b*SEQ + q)*DIM + h*64 + d]
    float inv0 = 1.0f / lrow[ty * 4 + 0];
    float inv1 = 1.0f / lrow[ty * 4 + 1];
    float inv2 = 1.0f / lrow[ty * 4 + 2];
    float inv3 = 1.0f / lrow[ty * 4 + 3];
    float* Ob = O + (size_t)b * SEQ * DIM + (size_t)h * HDIM;
    #pragma unroll
    for (int j = 0; j < 4; j++) {
        int c = tx * 4 + j;
        Ob[(size_t)(q0 + ty * 4 + 0) * DIM + c] = o[0][j] * inv0;
        Ob[(size_t)(q0 + ty * 4 + 1) * DIM + c] = o[1][j] * inv1;
        Ob[(size_t)(q0 + ty * 4 + 2) * DIM + c] = o[2][j] * inv2;
        Ob[(size_t)(q0 + ty * 4 + 3) * DIM + c] = o[3][j] * inv3;
    }
}

// ---------------- layernorm ----------------
__global__ __launch_bounds__(256) void ln_kernel(
    const float* __restrict__ x, const float* __restrict__ g,
    const float* __restrict__ be, float* __restrict__ out)
{
    const int row = blockIdx.x;
    const int t = threadIdx.x;
    const float* xr = x + (size_t)row * DIM;
    float v0 = xr[t], v1 = xr[t + 256];
    float s = v0 + v1, sq = v0 * v0 + v1 * v1;
    #pragma unroll
    for (int o = 16; o > 0; o >>= 1) {
        s  += __shfl_xor_sync(0xffffffffu, s, o);
        sq += __shfl_xor_sync(0xffffffffu, sq, o);
    }
    __shared__ float ps[8], pq[8];
    __shared__ float mu_s, inv_s;
    if ((t & 31) == 0) { ps[t >> 5] = s; pq[t >> 5] = sq; }
    __syncthreads();
    if (t == 0) {
        float S = 0.0f, Qq = 0.0f;
        #pragma unroll
        for (int i = 0; i < 8; i++) { S += ps[i]; Qq += pq[i]; }
        float mu = S * (1.0f / DIM);
        float var = Qq * (1.0f / DIM) - mu * mu;
        mu_s = mu;
        inv_s = rsqrtf(var + 1e-5f);
    }
    __syncthreads();
    float mu = mu_s, inv = inv_s;
    out[(size_t)row * DIM + t]       = (v0 - mu) * inv * g[t]       + be[t];
    out[(size_t)row * DIM + t + 256] = (v1 - mu) * inv * g[t + 256] + be[t + 256];
}

// ---------------- launch ----------------
extern "C" void kernel_launch(void* const* d_in, const int* in_sizes, int n_in,
                              void* d_out, int out_size)
{
    const float* x   = (const float*)d_in[0];
    const float* wq  = (const float*)d_in[1];
    const float* bq  = (const float*)d_in[2];
    const float* wk  = (const float*)d_in[3];
    const float* bk  = (const float*)d_in[4];
    const float* wv  = (const float*)d_in[5];
    const float* bv  = (const float*)d_in[6];
    const float* wo  = (const float*)d_in[7];
    const float* bo  = (const float*)d_in[8];
    const float* w1  = (const float*)d_in[9];
    const float* b1  = (const float*)d_in[10];
    const float* w2  = (const float*)d_in[11];
    const float* b2  = (const float*)d_in[12];
    const float* g1  = (const float*)d_in[13];
    const float* be1 = (const float*)d_in[14];
    const float* g2  = (const float*)d_in[15];
    const float* be2 = (const float*)d_in[16];
    float* out = (float*)d_out;

    float *q, *k, *v, *att, *y1, *x1, *hbuf, *y2;
    cudaGetSymbolAddress((void**)&q,    g_q);
    cudaGetSymbolAddress((void**)&k,    g_k);
    cudaGetSymbolAddress((void**)&v,    g_v);
    cudaGetSymbolAddress((void**)&att,  g_att);
    cudaGetSymbolAddress((void**)&y1,   g_y1);
    cudaGetSymbolAddress((void**)&x1,   g_x1);
    cudaGetSymbolAddress((void**)&hbuf, g_h);
    cudaGetSymbolAddress((void**)&y2,   g_y2);

    dim3 gD(DIM / BN, MTOT / BM);     // 8 x 128
    dim3 gF(FFN / BN, MTOT / BM);     // 32 x 128

    // QKV projections
    gemm_kernel<0><<<gD, 256>>>(x, wq, bq, nullptr, q, MTOT, DIM, DIM);
    gemm_kernel<0><<<gD, 256>>>(x, wk, bk, nullptr, k, MTOT, DIM, DIM);
    gemm_kernel<0><<<gD, 256>>>(x, wv, bv, nullptr, v, MTOT, DIM, DIM);

    // attention
    attn_kernel<<<dim3(SEQ / AQ, BATCH * NHEAD), 256>>>(q, k, v, att);

    // output projection + residual
    gemm_kernel<1><<<gD, 256>>>(att, wo, bo, x, y1, MTOT, DIM, DIM);
    ln_kernel<<<MTOT, 256>>>(y1, g1, be1, x1);

    // FFN
    gemm_kernel<2><<<gF, 256>>>(x1, w1, b1, nullptr, hbuf, MTOT, FFN, DIM);
    gemm_kernel<1><<<gD, 256>>>(hbuf, w2, b2, x1, y2, MTOT, DIM, FFN);
    ln_kernel<<<MTOT, 256>>>(y2, g2, be2, out);
}

// round 4
// speedup vs baseline: 1.0452x; 1.0452x over previous
#include <cuda_runtime.h>
#include <cuda_bf16.h>
#include <math.h>

// ---------------- problem constants ----------------
#define BATCH 4
#define SEQ   2048
#define DIM   512
#define NHEAD 8
#define HDIM  64
#define FFN   2048
#define MTOT  (BATCH * SEQ)          // 8192 rows

// ---------------- scratch (no allocation allowed) ----------------
__device__ float g_q  [MTOT * DIM];
__device__ float g_k  [MTOT * DIM];
__device__ float g_v  [MTOT * DIM];
__device__ float g_att[MTOT * DIM];
__device__ float g_y1 [MTOT * DIM];
__device__ float g_x1 [MTOT * DIM];
__device__ float g_h  [MTOT * FFN];
__device__ float g_y2 [MTOT * DIM];

__device__ __forceinline__ float gelu_exact(float v) {
    return 0.5f * v * (1.0f + erff(v * 0.70710678118654752f));
}

// ---------------- tiled SGEMM: 128x64 tile, 8x4 microtile, double-buffered ----
// C[M,N] = A[M,K] @ B[K,N] + bias[N] (+ residual / gelu)
// EPI: 0 = bias, 1 = bias + residual, 2 = bias + exact GELU
#define BM 128
#define BN 64
#define BK 16
#define ASTRIDE (BM + 4)   // 132 ; (132 % 32)==4 -> conflict-free patterns below

template<int EPI>
__device__ __forceinline__ void gemm_body(
    const float* __restrict__ A, const float* __restrict__ B,
    const float* __restrict__ bias, const float* __restrict__ res,
    float* __restrict__ C, int M, int N, int K)
{
    __shared__ float As[2][BK][ASTRIDE];
    __shared__ float Bs[2][BK][BN];

    const int tid = threadIdx.x;
    const int tx  = tid & 15;          // 0..15 -> cols tx*4
    const int ty  = tid >> 4;          // 0..15 -> rows ty*8
    const int rowBase = blockIdx.y * BM;
    const int colBase = blockIdx.x * BN;

    // A tile 128x16 load mapping: lane-per-row (conflict-free transposed scatter)
    const int lane = tid & 31;
    const int g    = (tid >> 5) & 3;   // col group -> c0 = g*4
    const int hh   = tid >> 7;         // 0/1
    const int aRow = lane + 32 * hh;   // 0..63 ; also +64
    const int aCol = g * 4;
    // B tile 16x64
    const int bRow = tid >> 4;
    const int bCol = (tid & 15) * 4;

    const float* Ap0 = A + (size_t)(rowBase + aRow) * K + aCol;
    const float* Ap1 = A + (size_t)(rowBase + aRow + 64) * K + aCol;
    const float* Bp  = B + (size_t)bRow * N + colBase + bCol;

    float4 a0 = *(const float4*)Ap0;
    float4 a1 = *(const float4*)Ap1;
    float4 b0 = *(const float4*)Bp;

    float acc[8][4] = {};

    int buf = 0;
    // store prologue tile
    As[0][aCol + 0][aRow] = a0.x; As[0][aCol + 1][aRow] = a0.y;
    As[0][aCol + 2][aRow] = a0.z; As[0][aCol + 3][aRow] = a0.w;
    As[0][aCol + 0][aRow + 64] = a1.x; As[0][aCol + 1][aRow + 64] = a1.y;
    As[0][aCol + 2][aRow + 64] = a1.z; As[0][aCol + 3][aRow + 64] = a1.w;
    *(float4*)&Bs[0][bRow][bCol] = b0;
    __syncthreads();

    for (int k0 = BK;; k0 += BK) {
        const bool more = (k0 < K);
        if (more) {
            a0 = *(const float4*)(Ap0 + k0);
            a1 = *(const float4*)(Ap1 + k0);
            b0 = *(const float4*)(Bp + (size_t)k0 * N);
        }

        #pragma unroll
        for (int kk = 0; kk < BK; kk++) {
            float4 ar0 = *(const float4*)&As[buf][kk][ty * 8];
            float4 ar1 = *(const float4*)&As[buf][kk][ty * 8 + 4];
            float4 br  = *(const float4*)&Bs[buf][kk][tx * 4];
            float av[8] = {ar0.x, ar0.y, ar0.z, ar0.w, ar1.x, ar1.y, ar1.z, ar1.w};
            #pragma unroll
            for (int i = 0; i < 8; i++) {
                acc[i][0] = fmaf(av[i], br.x, acc[i][0]);
                acc[i][1] = fmaf(av[i], br.y, acc[i][1]);
                acc[i][2] = fmaf(av[i], br.z, acc[i][2]);
                acc[i][3] = fmaf(av[i], br.w, acc[i][3]);
            }
        }
        if (!more) break;

        const int nb = buf ^ 1;
        As[nb][aCol + 0][aRow] = a0.x; As[nb][aCol + 1][aRow] = a0.y;
        As[nb][aCol + 2][aRow] = a0.z; As[nb][aCol + 3][aRow] = a0.w;
        As[nb][aCol + 0][aRow + 64] = a1.x; As[nb][aCol + 1][aRow + 64] = a1.y;
        As[nb][aCol + 2][aRow + 64] = a1.z; As[nb][aCol + 3][aRow + 64] = a1.w;
        *(float4*)&Bs[nb][bRow][bCol] = b0;
        buf = nb;
        __syncthreads();
    }

    // epilogue
    const float4 bb = *(const float4*)(bias + colBase + tx * 4);
    #pragma unroll
    for (int i = 0; i < 8; i++) {
        const int r = rowBase + ty * 8 + i;
        float4 v;
        v.x = acc[i][0] + bb.x; v.y = acc[i][1] + bb.y;
        v.z = acc[i][2] + bb.z; v.w = acc[i][3] + bb.w;
        if (EPI == 1) {
            float4 rr = *(const float4*)(res + (size_t)r * N + colBase + tx * 4);
            v.x += rr.x; v.y += rr.y; v.z += rr.z; v.w += rr.w;
        }
        if (EPI == 2) {
            v.x = gelu_exact(v.x); v.y = gelu_exact(v.y);
            v.z = gelu_exact(v.z); v.w = gelu_exact(v.w);
        }
        *(float4*)(C + (size_t)r * N + colBase + tx * 4) = v;
    }
}

template<int EPI>
__global__ __launch_bounds__(256) void gemm_kernel(
    const float* __restrict__ A, const float* __restrict__ B,
    const float* __restrict__ bias, const float* __restrict__ res,
    float* __restrict__ C, int M, int N, int K)
{
    gemm_body<EPI>(A, B, bias, res, C, M, N, K);
}

// fused QKV: gridDim.z selects which projection
__global__ __launch_bounds__(256) void qkv_kernel(
    const float* __restrict__ x,
    const float* __restrict__ wq, const float* __restrict__ bq, float* __restrict__ q,
    const float* __restrict__ wk, const float* __restrict__ bk, float* __restrict__ k,
    const float* __restrict__ wv, const float* __restrict__ bv, float* __restrict__ v)
{
    const float* W; const float* Bi; float* C;
    if (blockIdx.z == 0)      { W = wq; Bi = bq; C = q; }
    else if (blockIdx.z == 1) { W = wk; Bi = bk; C = k; }
    else                      { W = wv; Bi = bv; C = v; }
    gemm_body<0>(x, W, Bi, nullptr, C, MTOT, DIM, DIM);
}

// ---------------- flash attention (fp32), AQ=64, AK=64 ----------------
#define AQ 64
#define AK 64
#define PAD 4
#define AST (AK + PAD)   // 68 ; 68 % 32 == 4

__global__ __launch_bounds__(256) void attn_kernel(
    const float* __restrict__ Q, const float* __restrict__ K,
    const float* __restrict__ V, float* __restrict__ O)
{
    extern __shared__ float sm[];
    float* Qs = sm;                    // [HDIM][AST]  (d-major, q fast)
    float* Ks = Qs + HDIM * AST;       // [HDIM][AST]  (d-major, k fast)
    float* Vs = Ks + HDIM * AST;       // [AK][AST]    (k-major, d fast)
    float* Ss = Vs + AK * AST;         // [AQ][AST]    (q-major, k fast)
    float* mrow = Ss + AQ * AST;
    float* lrow = mrow + AQ;
    float* arow = lrow + AQ;

#define QS(d,qq) Qs[(d)*AST+(qq)]
#define KS(d,kk) Ks[(d)*AST+(kk)]
#define VS(kk,d) Vs[(kk)*AST+(d)]
#define SS(qq,kk) Ss[(qq)*AST+(kk)]

    const int tid = threadIdx.x;
    const int tx  = tid & 15;          // 0..15
    const int ty  = tid >> 4;          // 0..15
    const int lane = tid & 31;
    const int d0   = (tid >> 5) * 8;   // 0,8,...,56
    const int bh = blockIdx.y;
    const int b  = bh >> 3;
    const int h  = bh & 7;
    const int q0 = blockIdx.x * AQ;
    const float scale = 0.125f;        // 1/sqrt(64)

    const float* Qb = Q + (size_t)b * SEQ * DIM + (size_t)h * HDIM;
    const float* Kb = K + (size_t)b * SEQ * DIM + (size_t)h * HDIM;
    const float* Vb = V + (size_t)b * SEQ * DIM + (size_t)h * HDIM;

    // load Q tile, transposed scatter (conflict-free: lane indexes q)
    {
        const float* p0 = Qb + (size_t)(q0 + lane) * DIM + d0;
        const float* p1 = Qb + (size_t)(q0 + lane + 32) * DIM + d0;
        float4 u0 = *(const float4*)p0;
        float4 u1 = *(const float4*)(p0 + 4);
        float4 u2 = *(const float4*)p1;
        float4 u3 = *(const float4*)(p1 + 4);
        QS(d0 + 0, lane) = u0.x; QS(d0 + 1, lane) = u0.y;
        QS(d0 + 2, lane) = u0.z; QS(d0 + 3, lane) = u0.w;
        QS(d0 + 4, lane) = u1.x; QS(d0 + 5, lane) = u1.y;
        QS(d0 + 6, lane) = u1.z; QS(d0 + 7, lane) = u1.w;
        QS(d0 + 0, lane + 32) = u2.x; QS(d0 + 1, lane + 32) = u2.y;
        QS(d0 + 2, lane + 32) = u2.z; QS(d0 + 3, lane + 32) = u2.w;
        QS(d0 + 4, lane + 32) = u3.x; QS(d0 + 5, lane + 32) = u3.y;
        QS(d0 + 6, lane + 32) = u3.z; QS(d0 + 7, lane + 32) = u3.w;
    }
    if (tid < AQ) { mrow[tid] = -1e30f; lrow[tid] = 0.0f; }

    float o[4][4] = {};

    for (int t = 0; t < SEQ / AK; t++) {
        __syncthreads();   // previous tile fully consumed
        // load K (transposed scatter) and V (row-major) tiles
        {
            const float* kp0 = Kb + (size_t)(t * AK + lane) * DIM + d0;
            const float* kp1 = kp0 + (size_t)32 * DIM;
            float4 k0v = *(const float4*)kp0;
            float4 k1v = *(const float4*)(kp0 + 4);
            float4 k2v = *(const float4*)kp1;
            float4 k3v = *(const float4*)(kp1 + 4);
            KS(d0 + 0, lane) = k0v.x; KS(d0 + 1, lane) = k0v.y;
            KS(d0 + 2, lane) = k0v.z; KS(d0 + 3, lane) = k0v.w;
            KS(d0 + 4, lane) = k1v.x; KS(d0 + 5, lane) = k1v.y;
            KS(d0 + 6, lane) = k1v.z; KS(d0 + 7, lane) = k1v.w;
            KS(d0 + 0, lane + 32) = k2v.x; KS(d0 + 1, lane + 32) = k2v.y;
            KS(d0 + 2, lane + 32) = k2v.z; KS(d0 + 3, lane + 32) = k2v.w;
            KS(d0 + 4, lane + 32) = k3v.x; KS(d0 + 5, lane + 32) = k3v.y;
            KS(d0 + 6, lane + 32) = k3v.z; KS(d0 + 7, lane + 32) = k3v.w;

            const float* vp0 = Vb + (size_t)(t * AK + lane) * DIM + d0;
            const float* vp1 = vp0 + (size_t)32 * DIM;
            float4 v0v = *(const float4*)vp0;
            float4 v1v = *(const float4*)(vp0 + 4);
            float4 v2v = *(const float4*)vp1;
            float4 v3v = *(const float4*)(vp1 + 4);
            *(float4*)&VS(lane, d0)          = v0v;
            *(float4*)&VS(lane, d0 + 4)      = v1v;
            *(float4*)&VS(lane + 32, d0)     = v2v;
            *(float4*)&VS(lane + 32, d0 + 4) = v3v;
        }
        __syncthreads();

        // S = Q @ K^T (4x4 microtile, float4 operands)
        float s[4][4] = {};
        #pragma unroll 16
        for (int d = 0; d < HDIM; d++) {
            float4 aq = *(const float4*)&QS(d, ty * 4);
            float4 bk = *(const float4*)&KS(d, tx * 4);
            s[0][0] = fmaf(aq.x, bk.x, s[0][0]); s[0][1] = fmaf(aq.x, bk.y, s[0][1]);
            s[0][2] = fmaf(aq.x, bk.z, s[0][2]); s[0][3] = fmaf(aq.x, bk.w, s[0][3]);
            s[1][0] = fmaf(aq.y, bk.x, s[1][0]); s[1][1] = fmaf(aq.y, bk.y, s[1][1]);
            s[1][2] = fmaf(aq.y, bk.z, s[1][2]); s[1][3] = fmaf(aq.y, bk.w, s[1][3]);
            s[2][0] = fmaf(aq.z, bk.x, s[2][0]); s[2][1] = fmaf(aq.z, bk.y, s[2][1]);
            s[2][2] = fmaf(aq.z, bk.z, s[2][2]); s[2][3] = fmaf(aq.z, bk.w, s[2][3]);
            s[3][0] = fmaf(aq.w, bk.x, s[3][0]); s[3][1] = fmaf(aq.w, bk.y, s[3][1]);
            s[3][2] = fmaf(aq.w, bk.z, s[3][2]); s[3][3] = fmaf(aq.w, bk.w, s[3][3]);
        }
        #pragma unroll
        for (int i = 0; i < 4; i++) {
            float4 w = make_float4(s[i][0] * scale, s[i][1] * scale,
                                   s[i][2] * scale, s[i][3] * scale);
            *(float4*)&SS(ty * 4 + i, tx * 4) = w;
        }
        __syncthreads();

        // online softmax: 4 threads per row, 16 elems each
        {
            const int r = tid >> 2;
            const int p = tid & 3;
            float* row = &SS(r, p * 16);
            float4 e0 = *(float4*)(row + 0);
            float4 e1 = *(float4*)(row + 4);
            float4 e2 = *(float4*)(row + 8);
            float4 e3 = *(float4*)(row + 12);
            const float mold = mrow[r];
            float mx = fmaxf(fmaxf(fmaxf(e0.x, e0.y), fmaxf(e0.z, e0.w)),
                             fmaxf(fmaxf(e1.x, e1.y), fmaxf(e1.z, e1.w)));
            mx = fmaxf(mx, fmaxf(fmaxf(fmaxf(e2.x, e2.y), fmaxf(e2.z, e2.w)),
                                 fmaxf(fmaxf(e3.x, e3.y), fmaxf(e3.z, e3.w))));
            mx = fmaxf(mx, __shfl_xor_sync(0xffffffffu, mx, 1));
            mx = fmaxf(mx, __shfl_xor_sync(0xffffffffu, mx, 2));
            mx = fmaxf(mx, mold);
            e0.x = __expf(e0.x - mx); e0.y = __expf(e0.y - mx);
            e0.z = __expf(e0.z - mx); e0.w = __expf(e0.w - mx);
            e1.x = __expf(e1.x - mx); e1.y = __expf(e1.y - mx);
            e1.z = __expf(e1.z - mx); e1.w = __expf(e1.w - mx);
            e2.x = __expf(e2.x - mx); e2.y = __expf(e2.y - mx);
            e2.z = __expf(e2.z - mx); e2.w = __expf(e2.w - mx);
            e3.x = __expf(e3.x - mx); e3.y = __expf(e3.y - mx);
            e3.z = __expf(e3.z - mx); e3.w = __expf(e3.w - mx);
            *(float4*)(row + 0)  = e0;
            *(float4*)(row + 4)  = e1;
            *(float4*)(row + 8)  = e2;
            *(float4*)(row + 12) = e3;
            float sum = (e0.x + e0.y + e0.z + e0.w) + (e1.x + e1.y + e1.z + e1.w)
                      + (e2.x + e2.y + e2.z + e2.w) + (e3.x + e3.y + e3.z + e3.w);
            sum += __shfl_xor_sync(0xffffffffu, sum, 1);
            sum += __shfl_xor_sync(0xffffffffu, sum, 2);
            if (p == 0) {
                const float al = __expf(mold - mx);
                arow[r] = al;
                lrow[r] = lrow[r] * al + sum;
                mrow[r] = mx;
            }
        }
        __syncthreads();

        // O = O*alpha + P @ V
        {
            const float al0 = arow[ty * 4 + 0];
            const float al1 = arow[ty * 4 + 1];
            const float al2 = arow[ty * 4 + 2];
            const float al3 = arow[ty * 4 + 3];
            #pragma unroll
            for (int j = 0; j < 4; j++) {
                o[0][j] *= al0; o[1][j] *= al1; o[2][j] *= al2; o[3][j] *= al3;
            }
            #pragma unroll 16
            for (int kk = 0; kk < AK; kk++) {
                const float a0 = SS(ty * 4 + 0, kk);
                const float a1 = SS(ty * 4 + 1, kk);
                const float a2 = SS(ty * 4 + 2, kk);
                const float a3 = SS(ty * 4 + 3, kk);
                float4 bv = *(const float4*)&VS(kk, tx * 4);
                o[0][0] = fmaf(a0, bv.x, o[0][0]); o[0][1] = fmaf(a0, bv.y, o[0][1]);
                o[0][2] = fmaf(a0, bv.z, o[0][2]); o[0][3] = fmaf(a0, bv.w, o[0][3]);
                o[1][0] = fmaf(a1, bv.x, o[1][0]); o[1][1] = fmaf(a1, bv.y, o[1][1]);
                o[1][2] = fmaf(a1, bv.z, o[1][2]); o[1][3] = fmaf(a1, bv.w, o[1][3]);
                o[2][0] = fmaf(a2, bv.x, o[2][0]); o[2][1] = fmaf(a2, bv.y, o[2][1]);
                o[2][2] = fmaf(a2, bv.z, o[2][2]); o[2][3] = fmaf(a2, bv.w, o[2][3]);
                o[3][0] = fmaf(a3, bv.x, o[3][0]); o[3][1] = fmaf(a3, bv.y, o[3][1]);
                o[3][2] = fmaf(a3, bv.z, o[3][2]); o[3][3] = fmaf(a3, bv.w, o[3][3]);
            }
        }
    }

    // normalize and write out
    const float inv0 = 1.0f / lrow[ty * 4 + 0];
    const float inv1 = 1.0f / lrow[ty * 4 + 1];
    const float inv2 = 1.0f / lrow[ty * 4 + 2];
    const float inv3 = 1.0f / lrow[ty * 4 + 3];
    float* Ob = O + (size_t)b * SEQ * DIM + (size_t)h * HDIM;
    {
        float4 w0 = make_float4(o[0][0] * inv0, o[0][1] * inv0, o[0][2] * inv0, o[0][3] * inv0);
        float4 w1 = make_float4(o[1][0] * inv1, o[1][1] * inv1, o[1][2] * inv1, o[1][3] * inv1);
        float4 w2 = make_float4(o[2][0] * inv2, o[2][1] * inv2, o[2][2] * inv2, o[2][3] * inv2);
        float4 w3 = make_float4(o[3][0] * inv3, o[3][1] * inv3, o[3][2] * inv3, o[3][3] * inv3);
        *(float4*)(Ob + (size_t)(q0 + ty * 4 + 0) * DIM + tx * 4) = w0;
        *(float4*)(Ob + (size_t)(q0 + ty * 4 + 1) * DIM + tx * 4) = w1;
        *(float4*)(Ob + (size_t)(q0 + ty * 4 + 2) * DIM + tx * 4) = w2;
        *(float4*)(Ob + (size_t)(q0 + ty * 4 + 3) * DIM + tx * 4) = w3;
    }
}

#define ATTN_SMEM ((2 * HDIM * AST + AK * AST + AQ * AST + 3 * AQ) * (int)sizeof(float))

// ---------------- layernorm ----------------
__global__ __launch_bounds__(256) void ln_kernel(
    const float* __restrict__ x, const float* __restrict__ g,
    const float* __restrict__ be, float* __restrict__ out)
{
    const int row = blockIdx.x;
    const int t = threadIdx.x;
    const float* xr = x + (size_t)row * DIM;
    float v0 = xr[t], v1 = xr[t + 256];
    float s = v0 + v1, sq = v0 * v0 + v1 * v1;
    #pragma unroll
    for (int o = 16; o > 0; o >>= 1) {
        s  += __shfl_xor_sync(0xffffffffu, s, o);
        sq += __shfl_xor_sync(0xffffffffu, sq, o);
    }
    __shared__ float ps[8], pq[8];
    __shared__ float mu_s, inv_s;
    if ((t & 31) == 0) { ps[t >> 5] = s; pq[t >> 5] = sq; }
    __syncthreads();
    if (t == 0) {
        float S = 0.0f, Qq = 0.0f;
        #pragma unroll
        for (int i = 0; i < 8; i++) { S += ps[i]; Qq += pq[i]; }
        float mu = S * (1.0f / DIM);
        float var = Qq * (1.0f / DIM) - mu * mu;
        mu_s = mu;
        inv_s = rsqrtf(var + 1e-5f);
    }
    __syncthreads();
    float mu = mu_s, inv = inv_s;
    out[(size_t)row * DIM + t]       = (v0 - mu) * inv * g[t]       + be[t];
    out[(size_t)row * DIM + t + 256] = (v1 - mu) * inv * g[t + 256] + be[t + 256];
}

// ---------------- launch ----------------
extern "C" void kernel_launch(void* const* d_in, const int* in_sizes, int n_in,
                              void* d_out, int out_size)
{
    const float* x   = (const float*)d_in[0];
    const float* wq  = (const float*)d_in[1];
    const float* bq  = (const float*)d_in[2];
    const float* wk  = (const float*)d_in[3];
    const float* bk  = (const float*)d_in[4];
    const float* wv  = (const float*)d_in[5];
    const float* bv  = (const float*)d_in[6];
    const float* wo  = (const float*)d_in[7];
    const float* bo  = (const float*)d_in[8];
    const float* w1  = (const float*)d_in[9];
    const float* b1  = (const float*)d_in[10];
    const float* w2  = (const float*)d_in[11];
    const float* b2  = (const float*)d_in[12];
    const float* g1  = (const float*)d_in[13];
    const float* be1 = (const float*)d_in[14];
    const float* g2  = (const float*)d_in[15];
    const float* be2 = (const float*)d_in[16];
    float* out = (float*)d_out;

    float *q, *k, *v, *att, *y1, *x1, *hbuf, *y2;
    cudaGetSymbolAddress((void**)&q,    g_q);
    cudaGetSymbolAddress((void**)&k,    g_k);
    cudaGetSymbolAddress((void**)&v,    g_v);
    cudaGetSymbolAddress((void**)&att,  g_att);
    cudaGetSymbolAddress((void**)&y1,   g_y1);
    cudaGetSymbolAddress((void**)&x1,   g_x1);
    cudaGetSymbolAddress((void**)&hbuf, g_h);
    cudaGetSymbolAddress((void**)&y2,   g_y2);

    cudaFuncSetAttribute(attn_kernel,
                         cudaFuncAttributeMaxDynamicSharedMemorySize, ATTN_SMEM);

    dim3 gD(DIM / BN, MTOT / BM);        // 8 x 64
    dim3 gQKV(DIM / BN, MTOT / BM, 3);   // fused QKV
    dim3 gF(FFN / BN, MTOT / BM);        // 32 x 64

    // QKV projections (fused launch)
    qkv_kernel<<<gQKV, 256>>>(x, wq, bq, q, wk, bk, k, wv, bv, v);

    // attention
    attn_kernel<<<dim3(SEQ / AQ, BATCH * NHEAD), 256, ATTN_SMEM>>>(q, k, v, att);

    // output projection + residual, LN1
    gemm_kernel<1><<<gD, 256>>>(att, wo, bo, x, y1, MTOT, DIM, DIM);
    ln_kernel<<<MTOT, 256>>>(y1, g1, be1, x1);

    // FFN
    gemm_kernel<2><<<gF, 256>>>(x1, w1, b1, nullptr, hbuf, MTOT, FFN, DIM);
    gemm_kernel<1><<<gD, 256>>>(hbuf, w2, b2, x1, y2, MTOT, DIM, FFN);
    ln_kernel<<<MTOT, 256>>>(y2, g2, be2, out);
}